// round 15
// baseline (speedup 1.0000x reference)
#include <cuda_runtime.h>
#include <cuda_fp16.h>
#include <math.h>
#include <stdint.h>

#define D_MODEL 1024
#define N_HEADS 16
#define HEAD_DIM 64
#define SEQ_L 2048
#define BATCH 2
#define M_TOTAL (BATCH * SEQ_L)   // 4096
#define NW (D_MODEL * D_MODEL)    // 1M
#define NX (M_TOTAL * D_MODEL)    // 4M

// ---------------- scratch (static device globals; no allocation) -------------
__device__ __align__(256) __half g_q[NX];
__device__ __align__(256) __half g_k[NX];
__device__ __align__(256) __half g_v[NX];
__device__ int g_ridx[SEQ_L * 2];

// global-row split-K partials: 32 bh x 16 chunks (+ completion counters)
__device__ float g_gm[512];
__device__ float g_gd[512];
__device__ __align__(256) float g_gacc[512 * HEAD_DIM];
__device__ int g_cnt[32];

__device__ __align__(256) __half g_xhi[NX];
__device__ __align__(256) __half g_ahi[NX];
__device__ __align__(256) __half g_whi[4 * NW];

// ---------------- baseline-ISA helpers ---------------------------------------
__device__ __forceinline__ uint32_t smem_to_u32(const void* p) {
    uint32_t a;
    asm("{ .reg .u64 t; cvta.to.shared.u64 t, %1; cvt.u32.u64 %0, t; }" : "=r"(a) : "l"(p));
    return a;
}
__device__ __forceinline__ void cp16(uint32_t s, const void* g) {
    asm volatile("cp.async.cg.shared.global [%0], [%1], 16;" :: "r"(s), "l"(g) : "memory");
}
#define CP_COMMIT() asm volatile("cp.async.commit_group;" ::: "memory")
#define CP_WAIT1()  asm volatile("cp.async.wait_group 1;" ::: "memory")

__device__ __forceinline__ void ldm4(uint32_t (&r)[4], uint32_t addr) {
    asm volatile("ldmatrix.sync.aligned.m8n8.x4.shared.b16 {%0,%1,%2,%3}, [%4];"
                 : "=r"(r[0]), "=r"(r[1]), "=r"(r[2]), "=r"(r[3]) : "r"(addr));
}
__device__ __forceinline__ void mma16816(float (&d)[4], const uint32_t (&a)[4],
                                         uint32_t b0, uint32_t b1) {
    asm volatile(
        "mma.sync.aligned.m16n8k16.row.col.f32.f16.f16.f32 "
        "{%0,%1,%2,%3}, {%4,%5,%6,%7}, {%8,%9}, {%0,%1,%2,%3};"
        : "+f"(d[0]), "+f"(d[1]), "+f"(d[2]), "+f"(d[3])
        : "r"(a[0]), "r"(a[1]), "r"(a[2]), "r"(a[3]), "r"(b0), "r"(b1));
}

// ---------------- Threefry-2x32 (JAX partitionable) --------------------------
__device__ __forceinline__ unsigned rotl32(unsigned x, int d) {
    return (x << d) | (x >> (32 - d));
}
__device__ void threefry2x32(unsigned k0, unsigned k1, unsigned c0, unsigned c1,
                             unsigned& o0, unsigned& o1) {
    unsigned k2 = k0 ^ k1 ^ 0x1BD11BDAu;
    unsigned x0 = c0 + k0, x1 = c1 + k1;
#define TF_RND(r) { x0 += x1; x1 = rotl32(x1, (r)); x1 ^= x0; }
    TF_RND(13) TF_RND(15) TF_RND(26) TF_RND(6)
    x0 += k1; x1 += k2 + 1u;
    TF_RND(17) TF_RND(29) TF_RND(16) TF_RND(24)
    x0 += k2; x1 += k0 + 2u;
    TF_RND(13) TF_RND(15) TF_RND(26) TF_RND(6)
    x0 += k0; x1 += k1 + 3u;
    TF_RND(17) TF_RND(29) TF_RND(16) TF_RND(24)
    x0 += k1; x1 += k2 + 4u;
    TF_RND(13) TF_RND(15) TF_RND(26) TF_RND(6)
    x0 += k2; x1 += k0 + 5u;
#undef TF_RND
    o0 = x0; o1 = x1;
}

// ---------------- fused prep: x->fp16 | w->fp16 | ridx + counter reset --------
__global__ __launch_bounds__(256) void prep_kernel(
    const float* __restrict__ x,
    const float* __restrict__ w0, const float* __restrict__ w1,
    const float* __restrict__ w2, const float* __restrict__ w3) {
    int blk = blockIdx.x;
    if (blk < 16384) {
        int i = blk * 256 + threadIdx.x;
        g_xhi[i] = __float2half_rn(x[i]);
    } else if (blk < 32768) {
        int i = (blk - 16384) * 256 + threadIdx.x;
        int wi = i >> 20;
        int off = i & (NW - 1);
        const float* src = (wi == 0) ? w0 : (wi == 1) ? w1 : (wi == 2) ? w2 : w3;
        g_whi[i] = __float2half_rn(src[off]);
    } else {
        int i = (blk - 32768) * 256 + threadIdx.x;
        if (i < 32) g_cnt[i] = 0;
        if (i < SEQ_L) {
#pragma unroll
            for (int c = 0; c < 2; ++c) {
                unsigned n = (unsigned)(2 * i + c);
                unsigned o0, o1;
                threefry2x32(0u, 42u, 0u, n, o0, o1);
                unsigned bits = o0 ^ o1;
                float u = __uint_as_float((bits >> 9) | 0x3f800000u) - 1.0f;
                g_ridx[2 * i + c] = (int)(u * (float)(i + 1));
            }
        }
    }
}

// ---------------- HMMA GEMM: CTA 128x256, warps 2(M)x4(N), tile 64x64 --------
// C[M,1024] = A[M,1024] * B[1024,1024]^T, single-term fp16, 16 K-stages of 64.
// Per K-stage: 1024 HMMA vs 1024 smem phases -> tensor-bound (2:1 in cycles).
// smem: 3 stages x (A 16KB + B 32KB) = 144KB, occ 1 (8 warps/SM preserved).
#define STAGE_BYTES 49152
#define GEMM_SMEM (3 * STAGE_BYTES)
#define NSTAGES 16

__global__ __launch_bounds__(256, 1) void gemm_hmma_kernel(
    const __half* __restrict__ Ahi,
    const __half* __restrict__ Wh_base,
    __half* __restrict__ hq, __half* __restrict__ hk, __half* __restrict__ hv,
    float* __restrict__ fout,
    const float* __restrict__ freqs, int rope) {
    extern __shared__ __align__(128) char smem[];

    const int tid = threadIdx.x;
    const int lane = tid & 31;
    const int wid = tid >> 5;      // 0..7
    const int wm = wid >> 2;       // 0..1 (M 64-row halves)
    const int wn = wid & 3;        // 0..3 (N 64-col quarters)
    const int Mbase = blockIdx.y * 128;
    const int Nbase = blockIdx.x * 256;
    const int z = blockIdx.z;

    const __half* Bhi = Wh_base + (size_t)z * NW;
    __half* H = (z == 0) ? hq : (z == 1) ? hk : hv;

    uint32_t sbase = smem_to_u32(smem);

    // loader mapping: rows of 64 fp16 = 8 x 16B chunks.
    // A: 1024 chunks (4/thread); B: 2048 chunks (8/thread).
    const int ld_r0 = tid >> 3;   // 0..31
    const int ld_c = tid & 7;
    // (it*32) % 8 == 0 -> swizzle offset affine in it
    const uint32_t sw0 = (uint32_t)(ld_r0 * 128 + ((ld_c ^ (ld_r0 & 7)) << 4));

    float acc[4][8][4];
#pragma unroll
    for (int mt = 0; mt < 4; ++mt)
#pragma unroll
        for (int np = 0; np < 8; ++np)
#pragma unroll
            for (int e = 0; e < 4; ++e) acc[mt][np][e] = 0.f;

    const int arow_l = lane & 15;
    const int achk_l = lane >> 4;
    const int brow_l = (lane & 7) + ((lane >> 4) << 3);
    const int bchk_l = (lane >> 3) & 1;

#pragma unroll
    for (int ps = 0; ps < 2; ++ps) {
        const int ko = ps * 64;
        const uint32_t dst = sbase + ps * STAGE_BYTES;
        const __half* Ag = Ahi + (size_t)(Mbase + ld_r0) * 1024 + ko + ld_c * 8;
        const __half* Bg = Bhi + (size_t)(Nbase + ld_r0) * 1024 + ko + ld_c * 8;
#pragma unroll
        for (int it = 0; it < 4; ++it)
            cp16(dst + sw0 + it * 4096, Ag + (size_t)it * 32 * 1024);
#pragma unroll
        for (int it = 0; it < 8; ++it)
            cp16(dst + 16384 + sw0 + it * 4096, Bg + (size_t)it * 32 * 1024);
        CP_COMMIT();
    }

    for (int g = 0; g < NSTAGES; ++g) {
        const int buf = g % 3;
        const uint32_t sA = sbase + buf * STAGE_BYTES;
        const uint32_t sB = sA + 16384;
        CP_WAIT1();
        __syncthreads();

        {
            const int gn = g + 2;
            if (gn < NSTAGES) {
                const int ko = gn * 64;
                const uint32_t dst = sbase + (gn % 3) * STAGE_BYTES;
                const __half* Ag = Ahi + (size_t)(Mbase + ld_r0) * 1024 + ko + ld_c * 8;
                const __half* Bg = Bhi + (size_t)(Nbase + ld_r0) * 1024 + ko + ld_c * 8;
#pragma unroll
                for (int it = 0; it < 4; ++it)
                    cp16(dst + sw0 + it * 4096, Ag + (size_t)it * 32 * 1024);
#pragma unroll
                for (int it = 0; it < 8; ++it)
                    cp16(dst + 16384 + sw0 + it * 4096, Bg + (size_t)it * 32 * 1024);
            }
            CP_COMMIT();
        }

#pragma unroll
        for (int ks = 0; ks < 4; ++ks) {
            uint32_t afr[4][4];
#pragma unroll
            for (int mt = 0; mt < 4; ++mt) {
                int r = wm * 64 + mt * 16 + arow_l;
                int c = ks * 2 + achk_l;
                ldm4(afr[mt], sA + (uint32_t)(r * 128 + ((c ^ (r & 7)) << 4)));
            }
            uint32_t bfr[4][4];
#pragma unroll
            for (int p = 0; p < 4; ++p) {
                int r = wn * 64 + p * 16 + brow_l;
                int c = ks * 2 + bchk_l;
                ldm4(bfr[p], sB + (uint32_t)(r * 128 + ((c ^ (r & 7)) << 4)));
            }
#pragma unroll
            for (int mt = 0; mt < 4; ++mt)
#pragma unroll
                for (int p = 0; p < 4; ++p) {
                    mma16816(acc[mt][2 * p],     afr[mt], bfr[p][0], bfr[p][1]);
                    mma16816(acc[mt][2 * p + 1], afr[mt], bfr[p][2], bfr[p][3]);
                }
        }
    }

    const int fp16out = (fout == nullptr);
    const int do_rope = rope && (z < 2);
#pragma unroll
    for (int mt = 0; mt < 4; ++mt) {
        int mr = Mbase + wm * 64 + mt * 16 + (lane >> 2);
#pragma unroll
        for (int np = 0; np < 8; ++np) {
            int nc = Nbase + wn * 64 + np * 8 + (lane & 3) * 2;
            float e0 = acc[mt][np][0], e1 = acc[mt][np][1];
            float e2 = acc[mt][np][2], e3 = acc[mt][np][3];
            if (do_rope) {
                int j = (nc & 63) >> 1;
                int t0 = mr & (SEQ_L - 1);
                int t1 = (mr + 8) & (SEQ_L - 1);
                float sn, cs;
                sincosf(freqs[t0 * 32 + j], &sn, &cs);
                float r0 = e0 * cs - e1 * sn, r1 = e0 * sn + e1 * cs;
                e0 = r0; e1 = r1;
                sincosf(freqs[t1 * 32 + j], &sn, &cs);
                float r2 = e2 * cs - e3 * sn, r3 = e2 * sn + e3 * cs;
                e2 = r2; e3 = r3;
            }
            if (fp16out) {
                *(__half2*)(H + (size_t)mr * 1024 + nc) =
                    __halves2half2(__float2half_rn(e0), __float2half_rn(e1));
                *(__half2*)(H + (size_t)(mr + 8) * 1024 + nc) =
                    __halves2half2(__float2half_rn(e2), __float2half_rn(e3));
            } else {
                float* p0 = fout + (size_t)mr * 1024 + nc;
                p0[0] = e0; p0[1] = e1;
                float* p1 = p0 + 8 * 1024;
                p1[0] = e2; p1[1] = e3;
            }
        }
    }
}

// ---------------- fp16 load helpers for attention -----------------------------
__device__ __forceinline__ float4 ld_h4(const __half* p) {
    uint2 raw = *(const uint2*)p;
    __half2 a = *(__half2*)&raw.x, b = *(__half2*)&raw.y;
    float2 fa = __half22float2(a), fb = __half22float2(b);
    return make_float4(fa.x, fa.y, fb.x, fb.y);
}
__device__ __forceinline__ float2 ld_h2(const __half* p) {
    __half2 a = *(const __half2*)p;
    return __half22float2(a);
}

// ---------------- fused attention: sparse rows + global row (incl. combine) ---
__global__ __launch_bounds__(256) void attn_fused_kernel() {
    const float scale = 0.125f;

    if (blockIdx.x >= 8192) {
        // ---- global-row split-K partial ----
        const int idx = blockIdx.x - 8192;
        const int chunk = idx & 15;
        const int h = (idx >> 4) & 15;
        const int b = idx >> 8;
        const int bh = b * N_HEADS + h;
        const int tid = threadIdx.x;
        const int wid = tid >> 5, lane = tid & 31;

        size_t rowq = ((size_t)b * SEQ_L) * D_MODEL + h * HEAD_DIM;
        float2 qv = ld_h2(g_q + rowq + 2 * lane);
        size_t kvbase = rowq + 2 * lane;

        float mx = -1e30f, den = 0.f, ax = 0.f, ay = 0.f;
        const int jstart = chunk * 128 + wid * 16;
        for (int j0 = jstart; j0 < jstart + 16; j0 += 4) {
            float d[4];
            float2 vv[4];
#pragma unroll
            for (int t = 0; t < 4; ++t) {
                float2 kv = ld_h2(g_k + kvbase + (size_t)(j0 + t) * D_MODEL);
                vv[t] = ld_h2(g_v + kvbase + (size_t)(j0 + t) * D_MODEL);
                d[t] = qv.x * kv.x + qv.y * kv.y;
            }
#pragma unroll
            for (int off = 16; off; off >>= 1)
#pragma unroll
                for (int t = 0; t < 4; ++t)
                    d[t] += __shfl_xor_sync(0xffffffffu, d[t], off);
            float m4 = fmaxf(fmaxf(d[0], d[1]), fmaxf(d[2], d[3])) * scale;
            float nm = fmaxf(mx, m4);
            float corr = expf(mx - nm);
            float w[4];
#pragma unroll
            for (int t = 0; t < 4; ++t) w[t] = expf(d[t] * scale - nm);
            den = den * corr + w[0] + w[1] + w[2] + w[3];
            ax = ax * corr + w[0] * vv[0].x + w[1] * vv[1].x + w[2] * vv[2].x + w[3] * vv[3].x;
            ay = ay * corr + w[0] * vv[0].y + w[1] * vv[1].y + w[2] * vv[2].y + w[3] * vv[3].y;
            mx = nm;
        }

        __shared__ float sm_m[8], sm_d[8];
        __shared__ float sm_acc[8][65];
        __shared__ int doComb;
        sm_m[wid] = mx;
        sm_d[wid] = den;
        sm_acc[wid][2 * lane] = ax;
        sm_acc[wid][2 * lane + 1] = ay;
        __syncthreads();

        if (wid == 0) {
            float gm = sm_m[0];
#pragma unroll
            for (int w2 = 1; w2 < 8; ++w2) gm = fmaxf(gm, sm_m[w2]);
            float dt = 0.f, fx = 0.f, fy = 0.f;
#pragma unroll
            for (int w2 = 0; w2 < 8; ++w2) {
                float f = expf(sm_m[w2] - gm);
                dt += sm_d[w2] * f;
                fx += sm_acc[w2][2 * lane] * f;
                fy += sm_acc[w2][2 * lane + 1] * f;
            }
            int oi = bh * 16 + chunk;
            if (lane == 0) { g_gm[oi] = gm; g_gd[oi] = dt; }
            g_gacc[oi * HEAD_DIM + 2 * lane] = fx;
            g_gacc[oi * HEAD_DIM + 2 * lane + 1] = fy;
            __threadfence();
        }
        __syncthreads();
        if (tid == 0) doComb = (atomicAdd(&g_cnt[bh], 1) == 15);
        __syncthreads();

        if (doComb && tid < 64) {
            __threadfence();
            const int c = tid;
            float gm = -1e30f;
#pragma unroll
            for (int k = 0; k < 16; ++k) gm = fmaxf(gm, g_gm[bh * 16 + k]);
            float dt = 0.f, fx = 0.f;
#pragma unroll
            for (int k = 0; k < 16; ++k) {
                float f = expf(g_gm[bh * 16 + k] - gm);
                dt += g_gd[bh * 16 + k] * f;
                fx += g_gacc[(bh * 16 + k) * HEAD_DIM + c] * f;
            }
            g_ahi[rowq + c] = __float2half_rn(fx / dt);
        }
        return;
    }

    // ---- sparse rows: half-warp paired slots ----
    int gtid = blockIdx.x * 256 + threadIdx.x;
    int w = gtid >> 5;
    int lane = gtid & 31;
    int i = w & (SEQ_L - 1);
    if (i == 0) return;
    int bh = w >> 11;
    int h = bh & (N_HEADS - 1);
    int b = bh >> 4;

    const int half = lane >> 4;
    const int l16 = lane & 15;

    size_t rowq = ((size_t)(b * SEQ_L + i)) * D_MODEL + h * HEAD_DIM;
    float4 q4 = ld_h4(g_q + rowq + 4 * l16);
    size_t kvcol = ((size_t)b * SEQ_L) * D_MODEL + h * HEAD_DIM + 4 * l16;

    int r0 = g_ridx[2 * i], r1 = g_ridx[2 * i + 1];

    float p[6];
    int js[6];
    unsigned vm = 0;
#pragma unroll
    for (int pp = 0; pp < 6; ++pp) {
        const int s = 2 * pp + half;   // 0..11
        int j; bool valid;
        if (s == 0)       { j = 0; valid = true; }
        else if (s <= 8)  { j = i - 8 + s; valid = (j >= 1); }
        else if (s <= 10) {
            j = (s == 9) ? r0 : r1;
            valid = (j >= 1) && (j <= i - 8) && ((s == 9) || (j != r0));
        } else            { j = 0; valid = false; }

        float d = 0.f;
        if (valid) {
            float4 k4 = ld_h4(g_k + kvcol + (size_t)j * D_MODEL);
            d = q4.x * k4.x + q4.y * k4.y + q4.z * k4.z + q4.w * k4.w;
        }
#pragma unroll
        for (int off = 8; off; off >>= 1) d += __shfl_xor_sync(0xffffffffu, d, off);
        float sv = -1e30f;
        if (valid) { sv = d * scale; vm |= 1u << pp; }
        p[pp] = sv;
        js[pp] = j;
    }

    float mxh = p[0];
#pragma unroll
    for (int pp = 1; pp < 6; ++pp) mxh = fmaxf(mxh, p[pp]);
    float mx = fmaxf(mxh, __shfl_xor_sync(0xffffffffu, mxh, 16));

    float denh = 0.f;
#pragma unroll
    for (int pp = 0; pp < 6; ++pp) {
        p[pp] = ((vm >> pp) & 1u) ? expf(p[pp] - mx) : 0.f;
        denh += p[pp];
    }
    float den = denh + __shfl_xor_sync(0xffffffffu, denh, 16);
    float inv = 1.f / den;

    float4 a4 = make_float4(0.f, 0.f, 0.f, 0.f);
#pragma unroll
    for (int pp = 0; pp < 6; ++pp) {
        if ((vm >> pp) & 1u) {
            float4 v4 = ld_h4(g_v + kvcol + (size_t)js[pp] * D_MODEL);
            a4.x += p[pp] * v4.x;
            a4.y += p[pp] * v4.y;
            a4.z += p[pp] * v4.z;
            a4.w += p[pp] * v4.w;
        }
    }
    a4.x += __shfl_xor_sync(0xffffffffu, a4.x, 16);
    a4.y += __shfl_xor_sync(0xffffffffu, a4.y, 16);
    a4.z += __shfl_xor_sync(0xffffffffu, a4.z, 16);
    a4.w += __shfl_xor_sync(0xffffffffu, a4.w, 16);

    if (half == 0) {
        a4.x *= inv; a4.y *= inv; a4.z *= inv; a4.w *= inv;
        union { __half2 h2v[2]; uint2 u; } Hi;
        Hi.h2v[0] = __halves2half2(__float2half_rn(a4.x), __float2half_rn(a4.y));
        Hi.h2v[1] = __halves2half2(__float2half_rn(a4.z), __float2half_rn(a4.w));
        *(uint2*)(g_ahi + rowq + 4 * l16) = Hi.u;
    }
}

// ---------------- launch ------------------------------------------------------
extern "C" void kernel_launch(void* const* d_in, const int* in_sizes, int n_in,
                              void* d_out, int out_size) {
    const float* x     = (const float*)d_in[0];
    const float* freqs = (const float*)d_in[1];
    const float* wq    = (const float*)d_in[2];
    const float* wk    = (const float*)d_in[3];
    const float* wv    = (const float*)d_in[4];
    const float* wo    = (const float*)d_in[5];
    float* out = (float*)d_out;

    __half *qp, *kp, *vp, *xhi, *ahi, *whi;
    cudaGetSymbolAddress((void**)&qp, g_q);
    cudaGetSymbolAddress((void**)&kp, g_k);
    cudaGetSymbolAddress((void**)&vp, g_v);
    cudaGetSymbolAddress((void**)&xhi, g_xhi);
    cudaGetSymbolAddress((void**)&ahi, g_ahi);
    cudaGetSymbolAddress((void**)&whi, g_whi);

    cudaFuncSetAttribute(gemm_hmma_kernel,
                         cudaFuncAttributeMaxDynamicSharedMemorySize, GEMM_SMEM);

    prep_kernel<<<32776, 256>>>(x, wq, wk, wv, wo);

    dim3 gqkv(1024 / 256, M_TOTAL / 128, 3);   // (4, 32, 3) = 384 CTAs
    gemm_hmma_kernel<<<gqkv, 256, GEMM_SMEM>>>(xhi, whi, qp, kp, vp,
                                               nullptr, freqs, 1);

    attn_fused_kernel<<<8704, 256>>>();

    dim3 go(1024 / 256, M_TOTAL / 128, 1);     // (4, 32, 1) = 128 CTAs, 1 wave
    gemm_hmma_kernel<<<go, 256, GEMM_SMEM>>>(ahi, whi + 3 * (size_t)NW,
                                             nullptr, nullptr, nullptr,
                                             out, freqs, 0);
}

// round 16
// speedup vs baseline: 1.1708x; 1.1708x over previous
#include <cuda_runtime.h>
#include <cuda_fp16.h>
#include <math.h>
#include <stdint.h>

#define D_MODEL 1024
#define N_HEADS 16
#define HEAD_DIM 64
#define SEQ_L 2048
#define BATCH 2
#define M_TOTAL (BATCH * SEQ_L)   // 4096
#define NW (D_MODEL * D_MODEL)    // 1M
#define NX (M_TOTAL * D_MODEL)    // 4M

// ---------------- scratch (static device globals; no allocation) -------------
__device__ __align__(256) __half g_q[NX];
__device__ __align__(256) __half g_k[NX];
__device__ __align__(256) __half g_v[NX];
__device__ int g_ridx[SEQ_L * 2];

// global-row split-K partials: 32 bh x 16 chunks (+ completion counters)
__device__ float g_gm[512];
__device__ float g_gd[512];
__device__ __align__(256) float g_gacc[512 * HEAD_DIM];
__device__ int g_cnt[32];

__device__ __align__(256) __half g_xhi[NX];
__device__ __align__(256) __half g_ahi[NX];
__device__ __align__(256) __half g_whi[4 * NW];

// ---------------- baseline-ISA helpers ---------------------------------------
__device__ __forceinline__ uint32_t smem_to_u32(const void* p) {
    uint32_t a;
    asm("{ .reg .u64 t; cvta.to.shared.u64 t, %1; cvt.u32.u64 %0, t; }" : "=r"(a) : "l"(p));
    return a;
}
__device__ __forceinline__ void cp16(uint32_t s, const void* g) {
    asm volatile("cp.async.cg.shared.global [%0], [%1], 16;" :: "r"(s), "l"(g) : "memory");
}
#define CP_COMMIT() asm volatile("cp.async.commit_group;" ::: "memory")
#define CP_WAIT1()  asm volatile("cp.async.wait_group 1;" ::: "memory")

__device__ __forceinline__ void ldm4(uint32_t (&r)[4], uint32_t addr) {
    asm volatile("ldmatrix.sync.aligned.m8n8.x4.shared.b16 {%0,%1,%2,%3}, [%4];"
                 : "=r"(r[0]), "=r"(r[1]), "=r"(r[2]), "=r"(r[3]) : "r"(addr));
}
__device__ __forceinline__ void mma16816(float (&d)[4], const uint32_t (&a)[4],
                                         uint32_t b0, uint32_t b1) {
    asm volatile(
        "mma.sync.aligned.m16n8k16.row.col.f32.f16.f16.f32 "
        "{%0,%1,%2,%3}, {%4,%5,%6,%7}, {%8,%9}, {%0,%1,%2,%3};"
        : "+f"(d[0]), "+f"(d[1]), "+f"(d[2]), "+f"(d[3])
        : "r"(a[0]), "r"(a[1]), "r"(a[2]), "r"(a[3]), "r"(b0), "r"(b1));
}

// ---------------- Threefry-2x32 (JAX partitionable) --------------------------
__device__ __forceinline__ unsigned rotl32(unsigned x, int d) {
    return (x << d) | (x >> (32 - d));
}
__device__ void threefry2x32(unsigned k0, unsigned k1, unsigned c0, unsigned c1,
                             unsigned& o0, unsigned& o1) {
    unsigned k2 = k0 ^ k1 ^ 0x1BD11BDAu;
    unsigned x0 = c0 + k0, x1 = c1 + k1;
#define TF_RND(r) { x0 += x1; x1 = rotl32(x1, (r)); x1 ^= x0; }
    TF_RND(13) TF_RND(15) TF_RND(26) TF_RND(6)
    x0 += k1; x1 += k2 + 1u;
    TF_RND(17) TF_RND(29) TF_RND(16) TF_RND(24)
    x0 += k2; x1 += k0 + 2u;
    TF_RND(13) TF_RND(15) TF_RND(26) TF_RND(6)
    x0 += k0; x1 += k1 + 3u;
    TF_RND(17) TF_RND(29) TF_RND(16) TF_RND(24)
    x0 += k1; x1 += k2 + 4u;
    TF_RND(13) TF_RND(15) TF_RND(26) TF_RND(6)
    x0 += k2; x1 += k0 + 5u;
#undef TF_RND
    o0 = x0; o1 = x1;
}

// ---------------- fused prep: x->fp16 | w->fp16 | ridx + counter reset --------
__global__ __launch_bounds__(256) void prep_kernel(
    const float* __restrict__ x,
    const float* __restrict__ w0, const float* __restrict__ w1,
    const float* __restrict__ w2, const float* __restrict__ w3) {
    int blk = blockIdx.x;
    if (blk < 16384) {
        int i = blk * 256 + threadIdx.x;
        g_xhi[i] = __float2half_rn(x[i]);
    } else if (blk < 32768) {
        int i = (blk - 16384) * 256 + threadIdx.x;
        int wi = i >> 20;
        int off = i & (NW - 1);
        const float* src = (wi == 0) ? w0 : (wi == 1) ? w1 : (wi == 2) ? w2 : w3;
        g_whi[i] = __float2half_rn(src[off]);
    } else {
        int i = (blk - 32768) * 256 + threadIdx.x;
        if (i < 32) g_cnt[i] = 0;
        if (i < SEQ_L) {
#pragma unroll
            for (int c = 0; c < 2; ++c) {
                unsigned n = (unsigned)(2 * i + c);
                unsigned o0, o1;
                threefry2x32(0u, 42u, 0u, n, o0, o1);
                unsigned bits = o0 ^ o1;
                float u = __uint_as_float((bits >> 9) | 0x3f800000u) - 1.0f;
                g_ridx[2 * i + c] = (int)(u * (float)(i + 1));
            }
        }
    }
}

// ---------------- HMMA GEMM (R14 config: 256 thr, warp tile 32x64, occ 2) ----
// C[M,1024] = A[M,1024] * B[1024,1024]^T, single-term fp16, 16 K-stages of 64.
// QKV launch: fp16 outputs (hq/hk/hv) + fused rope on z<2.
// O launch:   fp32 output (fout).
#define GEMM_SMEM (3 * 32768)
#define NSTAGES 16

__global__ __launch_bounds__(256, 2) void gemm_hmma_kernel(
    const __half* __restrict__ Ahi,
    const __half* __restrict__ Wh_base,
    __half* __restrict__ hq, __half* __restrict__ hk, __half* __restrict__ hv,
    float* __restrict__ fout,
    const float* __restrict__ freqs, int rope) {
    extern __shared__ __align__(128) char smem[];

    const int tid = threadIdx.x;
    const int lane = tid & 31;
    const int wid = tid >> 5;
    const int wm = wid >> 1;
    const int wn = wid & 1;
    const int Mbase = blockIdx.y * 128;
    const int Nbase = blockIdx.x * 128;
    const int z = blockIdx.z;

    const __half* Bhi = Wh_base + (size_t)z * NW;
    __half* H = (z == 0) ? hq : (z == 1) ? hk : hv;

    uint32_t sbase = smem_to_u32(smem);

    uint32_t sw_st[4];
    int ld_r[4], ld_c[4];
#pragma unroll
    for (int it = 0; it < 4; ++it) {
        int id = it * 256 + tid;
        int r = id >> 3, c = id & 7;
        ld_r[it] = r; ld_c[it] = c;
        sw_st[it] = (uint32_t)(r * 128 + ((c ^ (r & 7)) << 4));
    }

    float acc[2][8][4];
#pragma unroll
    for (int mt = 0; mt < 2; ++mt)
#pragma unroll
        for (int np = 0; np < 8; ++np)
#pragma unroll
            for (int e = 0; e < 4; ++e) acc[mt][np][e] = 0.f;

    const int arow_l = lane & 15;
    const int achk_l = lane >> 4;
    const int brow_l = (lane & 7) + ((lane >> 4) << 3);
    const int bchk_l = (lane >> 3) & 1;

#pragma unroll
    for (int ps = 0; ps < 2; ++ps) {
        const int ko = ps * 64;
        const uint32_t dst = sbase + ps * 32768;
#pragma unroll
        for (int it = 0; it < 4; ++it) {
            cp16(dst + sw_st[it], Ahi + (size_t)(Mbase + ld_r[it]) * 1024 + ko + ld_c[it] * 8);
            cp16(dst + 16384 + sw_st[it], Bhi + (size_t)(Nbase + ld_r[it]) * 1024 + ko + ld_c[it] * 8);
        }
        CP_COMMIT();
    }

    for (int g = 0; g < NSTAGES; ++g) {
        const int buf = g % 3;
        const uint32_t sA = sbase + buf * 32768;
        const uint32_t sB = sA + 16384;
        CP_WAIT1();
        __syncthreads();

        {
            const int gn = g + 2;
            if (gn < NSTAGES) {
                const int ko = gn * 64;
                const uint32_t dst = sbase + (gn % 3) * 32768;
#pragma unroll
                for (int it = 0; it < 4; ++it) {
                    cp16(dst + sw_st[it], Ahi + (size_t)(Mbase + ld_r[it]) * 1024 + ko + ld_c[it] * 8);
                    cp16(dst + 16384 + sw_st[it], Bhi + (size_t)(Nbase + ld_r[it]) * 1024 + ko + ld_c[it] * 8);
                }
            }
            CP_COMMIT();
        }

#pragma unroll
        for (int ks = 0; ks < 4; ++ks) {
            uint32_t afr[2][4];
#pragma unroll
            for (int mt = 0; mt < 2; ++mt) {
                int r = wm * 32 + mt * 16 + arow_l;
                int c = ks * 2 + achk_l;
                ldm4(afr[mt], sA + (uint32_t)(r * 128 + ((c ^ (r & 7)) << 4)));
            }
            uint32_t bfr[4][4];
#pragma unroll
            for (int p = 0; p < 4; ++p) {
                int r = wn * 64 + p * 16 + brow_l;
                int c = ks * 2 + bchk_l;
                ldm4(bfr[p], sB + (uint32_t)(r * 128 + ((c ^ (r & 7)) << 4)));
            }
#pragma unroll
            for (int mt = 0; mt < 2; ++mt)
#pragma unroll
                for (int p = 0; p < 4; ++p) {
                    mma16816(acc[mt][2 * p],     afr[mt], bfr[p][0], bfr[p][1]);
                    mma16816(acc[mt][2 * p + 1], afr[mt], bfr[p][2], bfr[p][3]);
                }
        }
    }

    const int fp16out = (fout == nullptr);
    const int do_rope = rope && (z < 2);
#pragma unroll
    for (int mt = 0; mt < 2; ++mt) {
        int mr = Mbase + wm * 32 + mt * 16 + (lane >> 2);
#pragma unroll
        for (int np = 0; np < 8; ++np) {
            int nc = Nbase + wn * 64 + np * 8 + (lane & 3) * 2;
            float e0 = acc[mt][np][0], e1 = acc[mt][np][1];
            float e2 = acc[mt][np][2], e3 = acc[mt][np][3];
            if (do_rope) {
                int j = (nc & 63) >> 1;
                int t0 = mr & (SEQ_L - 1);
                int t1 = (mr + 8) & (SEQ_L - 1);
                float sn, cs;
                sincosf(freqs[t0 * 32 + j], &sn, &cs);
                float r0 = e0 * cs - e1 * sn, r1 = e0 * sn + e1 * cs;
                e0 = r0; e1 = r1;
                sincosf(freqs[t1 * 32 + j], &sn, &cs);
                float r2 = e2 * cs - e3 * sn, r3 = e2 * sn + e3 * cs;
                e2 = r2; e3 = r3;
            }
            if (fp16out) {
                *(__half2*)(H + (size_t)mr * 1024 + nc) =
                    __halves2half2(__float2half_rn(e0), __float2half_rn(e1));
                *(__half2*)(H + (size_t)(mr + 8) * 1024 + nc) =
                    __halves2half2(__float2half_rn(e2), __float2half_rn(e3));
            } else {
                float* p0 = fout + (size_t)mr * 1024 + nc;
                p0[0] = e0; p0[1] = e1;
                float* p1 = p0 + 8 * 1024;
                p1[0] = e2; p1[1] = e3;
            }
        }
    }
}

// ---------------- fp16 load helpers for attention -----------------------------
__device__ __forceinline__ float4 ld_h4(const __half* p) {
    uint2 raw = *(const uint2*)p;
    __half2 a = *(__half2*)&raw.x, b = *(__half2*)&raw.y;
    float2 fa = __half22float2(a), fb = __half22float2(b);
    return make_float4(fa.x, fa.y, fb.x, fb.y);
}
__device__ __forceinline__ float2 ld_h2(const __half* p) {
    __half2 a = *(const __half2*)p;
    return __half22float2(a);
}

// ---------------- fused attention: sparse rows + global row (incl. combine) ---
__global__ __launch_bounds__(256) void attn_fused_kernel() {
    const float scale = 0.125f;

    if (blockIdx.x >= 8192) {
        // ---- global-row split-K partial ----
        const int idx = blockIdx.x - 8192;
        const int chunk = idx & 15;
        const int h = (idx >> 4) & 15;
        const int b = idx >> 8;
        const int bh = b * N_HEADS + h;
        const int tid = threadIdx.x;
        const int wid = tid >> 5, lane = tid & 31;

        size_t rowq = ((size_t)b * SEQ_L) * D_MODEL + h * HEAD_DIM;
        float2 qv = ld_h2(g_q + rowq + 2 * lane);
        size_t kvbase = rowq + 2 * lane;

        float mx = -1e30f, den = 0.f, ax = 0.f, ay = 0.f;
        const int jstart = chunk * 128 + wid * 16;
        for (int j0 = jstart; j0 < jstart + 16; j0 += 4) {
            float d[4];
            float2 vv[4];
#pragma unroll
            for (int t = 0; t < 4; ++t) {
                float2 kv = ld_h2(g_k + kvbase + (size_t)(j0 + t) * D_MODEL);
                vv[t] = ld_h2(g_v + kvbase + (size_t)(j0 + t) * D_MODEL);
                d[t] = qv.x * kv.x + qv.y * kv.y;
            }
#pragma unroll
            for (int off = 16; off; off >>= 1)
#pragma unroll
                for (int t = 0; t < 4; ++t)
                    d[t] += __shfl_xor_sync(0xffffffffu, d[t], off);
            float m4 = fmaxf(fmaxf(d[0], d[1]), fmaxf(d[2], d[3])) * scale;
            float nm = fmaxf(mx, m4);
            float corr = __expf(mx - nm);
            float w[4];
#pragma unroll
            for (int t = 0; t < 4; ++t) w[t] = __expf(d[t] * scale - nm);
            den = den * corr + w[0] + w[1] + w[2] + w[3];
            ax = ax * corr + w[0] * vv[0].x + w[1] * vv[1].x + w[2] * vv[2].x + w[3] * vv[3].x;
            ay = ay * corr + w[0] * vv[0].y + w[1] * vv[1].y + w[2] * vv[2].y + w[3] * vv[3].y;
            mx = nm;
        }

        __shared__ float sm_m[8], sm_d[8];
        __shared__ float sm_acc[8][65];
        __shared__ int doComb;
        sm_m[wid] = mx;
        sm_d[wid] = den;
        sm_acc[wid][2 * lane] = ax;
        sm_acc[wid][2 * lane + 1] = ay;
        __syncthreads();

        if (wid == 0) {
            float gm = sm_m[0];
#pragma unroll
            for (int w2 = 1; w2 < 8; ++w2) gm = fmaxf(gm, sm_m[w2]);
            float dt = 0.f, fx = 0.f, fy = 0.f;
#pragma unroll
            for (int w2 = 0; w2 < 8; ++w2) {
                float f = __expf(sm_m[w2] - gm);
                dt += sm_d[w2] * f;
                fx += sm_acc[w2][2 * lane] * f;
                fy += sm_acc[w2][2 * lane + 1] * f;
            }
            int oi = bh * 16 + chunk;
            if (lane == 0) { g_gm[oi] = gm; g_gd[oi] = dt; }
            g_gacc[oi * HEAD_DIM + 2 * lane] = fx;
            g_gacc[oi * HEAD_DIM + 2 * lane + 1] = fy;
            __threadfence();
        }
        __syncthreads();
        if (tid == 0) doComb = (atomicAdd(&g_cnt[bh], 1) == 15);
        __syncthreads();

        if (doComb && tid < 64) {
            __threadfence();
            const int c = tid;
            float gm = -1e30f;
#pragma unroll
            for (int k = 0; k < 16; ++k) gm = fmaxf(gm, g_gm[bh * 16 + k]);
            float dt = 0.f, fx = 0.f;
#pragma unroll
            for (int k = 0; k < 16; ++k) {
                float f = __expf(g_gm[bh * 16 + k] - gm);
                dt += g_gd[bh * 16 + k] * f;
                fx += g_gacc[(bh * 16 + k) * HEAD_DIM + c] * f;
            }
            g_ahi[rowq + c] = __float2half_rn(fx / dt);
        }
        return;
    }

    // ---- sparse rows: half-warp paired slots ----
    int gtid = blockIdx.x * 256 + threadIdx.x;
    int w = gtid >> 5;
    int lane = gtid & 31;
    int i = w & (SEQ_L - 1);
    if (i == 0) return;
    int bh = w >> 11;
    int h = bh & (N_HEADS - 1);
    int b = bh >> 4;

    const int half = lane >> 4;
    const int l16 = lane & 15;

    size_t rowq = ((size_t)(b * SEQ_L + i)) * D_MODEL + h * HEAD_DIM;
    float4 q4 = ld_h4(g_q + rowq + 4 * l16);
    size_t kvcol = ((size_t)b * SEQ_L) * D_MODEL + h * HEAD_DIM + 4 * l16;

    int r0 = g_ridx[2 * i], r1 = g_ridx[2 * i + 1];

    float p[6];
    int js[6];
    unsigned vm = 0;
#pragma unroll
    for (int pp = 0; pp < 6; ++pp) {
        const int s = 2 * pp + half;   // 0..11
        int j; bool valid;
        if (s == 0)       { j = 0; valid = true; }
        else if (s <= 8)  { j = i - 8 + s; valid = (j >= 1); }
        else if (s <= 10) {
            j = (s == 9) ? r0 : r1;
            valid = (j >= 1) && (j <= i - 8) && ((s == 9) || (j != r0));
        } else            { j = 0; valid = false; }

        float d = 0.f;
        if (valid) {
            float4 k4 = ld_h4(g_k + kvcol + (size_t)j * D_MODEL);
            d = q4.x * k4.x + q4.y * k4.y + q4.z * k4.z + q4.w * k4.w;
        }
#pragma unroll
        for (int off = 8; off; off >>= 1) d += __shfl_xor_sync(0xffffffffu, d, off);
        float sv = -1e30f;
        if (valid) { sv = d * scale; vm |= 1u << pp; }
        p[pp] = sv;
        js[pp] = j;
    }

    float mxh = p[0];
#pragma unroll
    for (int pp = 1; pp < 6; ++pp) mxh = fmaxf(mxh, p[pp]);
    float mx = fmaxf(mxh, __shfl_xor_sync(0xffffffffu, mxh, 16));

    float denh = 0.f;
#pragma unroll
    for (int pp = 0; pp < 6; ++pp) {
        p[pp] = ((vm >> pp) & 1u) ? __expf(p[pp] - mx) : 0.f;
        denh += p[pp];
    }
    float den = denh + __shfl_xor_sync(0xffffffffu, denh, 16);
    float inv = 1.f / den;

    float4 a4 = make_float4(0.f, 0.f, 0.f, 0.f);
#pragma unroll
    for (int pp = 0; pp < 6; ++pp) {
        if ((vm >> pp) & 1u) {
            float4 v4 = ld_h4(g_v + kvcol + (size_t)js[pp] * D_MODEL);
            a4.x += p[pp] * v4.x;
            a4.y += p[pp] * v4.y;
            a4.z += p[pp] * v4.z;
            a4.w += p[pp] * v4.w;
        }
    }
    a4.x += __shfl_xor_sync(0xffffffffu, a4.x, 16);
    a4.y += __shfl_xor_sync(0xffffffffu, a4.y, 16);
    a4.z += __shfl_xor_sync(0xffffffffu, a4.z, 16);
    a4.w += __shfl_xor_sync(0xffffffffu, a4.w, 16);

    if (half == 0) {
        a4.x *= inv; a4.y *= inv; a4.z *= inv; a4.w *= inv;
        union { __half2 h2v[2]; uint2 u; } Hi;
        Hi.h2v[0] = __halves2half2(__float2half_rn(a4.x), __float2half_rn(a4.y));
        Hi.h2v[1] = __halves2half2(__float2half_rn(a4.z), __float2half_rn(a4.w));
        *(uint2*)(g_ahi + rowq + 4 * l16) = Hi.u;
    }
}

// ---------------- launch ------------------------------------------------------
extern "C" void kernel_launch(void* const* d_in, const int* in_sizes, int n_in,
                              void* d_out, int out_size) {
    const float* x     = (const float*)d_in[0];
    const float* freqs = (const float*)d_in[1];
    const float* wq    = (const float*)d_in[2];
    const float* wk    = (const float*)d_in[3];
    const float* wv    = (const float*)d_in[4];
    const float* wo    = (const float*)d_in[5];
    float* out = (float*)d_out;

    __half *qp, *kp, *vp, *xhi, *ahi, *whi;
    cudaGetSymbolAddress((void**)&qp, g_q);
    cudaGetSymbolAddress((void**)&kp, g_k);
    cudaGetSymbolAddress((void**)&vp, g_v);
    cudaGetSymbolAddress((void**)&xhi, g_xhi);
    cudaGetSymbolAddress((void**)&ahi, g_ahi);
    cudaGetSymbolAddress((void**)&whi, g_whi);

    cudaFuncSetAttribute(gemm_hmma_kernel,
                         cudaFuncAttributeMaxDynamicSharedMemorySize, GEMM_SMEM);

    prep_kernel<<<32776, 256>>>(x, wq, wk, wv, wo);

    dim3 gqkv(1024 / 128, M_TOTAL / 128, 3);   // (8, 32, 3) = 768 CTAs
    gemm_hmma_kernel<<<gqkv, 256, GEMM_SMEM>>>(xhi, whi, qp, kp, vp,
                                               nullptr, freqs, 1);

    attn_fused_kernel<<<8704, 256>>>();

    dim3 go(1024 / 128, M_TOTAL / 128, 1);     // (8, 32, 1) = 256 CTAs
    gemm_hmma_kernel<<<go, 256, GEMM_SMEM>>>(ahi, whi + 3 * (size_t)NW,
                                             nullptr, nullptr, nullptr,
                                             out, freqs, 0);
}